// round 16
// baseline (speedup 1.0000x reference)
#include <cuda_runtime.h>
#include <cuda_bf16.h>
#include <cstdint>
#include <math.h>

#define DIMX   2048
#define INNERX 8192
#define TOKX   8192

// ------------------------- device-global scratch -------------------------
__device__ __nv_bfloat16 g_w1s[(size_t)INNERX * DIMX];   // sign(w1) in {-1,0,1} (bf16)
__device__ __nv_bfloat16 g_w2s[(size_t)DIMX * INNERX];   // sign(w2)
__device__ __nv_bfloat16 g_xq[(size_t)TOKX * DIMX];      // quantized activations (integer-valued bf16)
__device__ __nv_bfloat16 g_hq[(size_t)TOKX * INNERX];
__device__ float  g_h[(size_t)TOKX * INNERX];            // fp32 hidden after GELU
__device__ float  g_xsr[TOKX];                           // per-token 1/scale (layer 1)
__device__ float  g_hsr[TOKX];                           // per-token 1/scale (layer 2)
__device__ float  g_part1[1024];
__device__ float  g_part2[1024];
__device__ float  g_wscale[2];                           // mean|w1|, mean|w2|
__device__ float  g_hss[(size_t)TOKX * 64];              // per-(row, colTile) sum(h^2) partials
__device__ float  g_hmx[(size_t)TOKX * 64];              // per-(row, colTile) max|h| partials

// ------------------------- helpers -------------------------
__device__ __forceinline__ uint32_t smem_u32(const void* p) {
    uint32_t a;
    asm("{ .reg .u64 t; cvta.to.shared.u64 t, %1; cvt.u32.u64 %0, t; }" : "=r"(a) : "l"(p));
    return a;
}
#define SWZ128(b) ((b) ^ (((b) >> 3) & 0x70))

__device__ __forceinline__ void cp16(uint32_t dst, const void* src) {
    asm volatile("cp.async.cg.shared.global [%0], [%1], 16;" :: "r"(dst), "l"(src) : "memory");
}
#define CP_COMMIT() asm volatile("cp.async.commit_group;" ::: "memory")
#define CP_WAIT(n)  asm volatile("cp.async.wait_group %0;" :: "n"(n) : "memory")

__device__ __forceinline__ void ldsm4(uint32_t& r0, uint32_t& r1, uint32_t& r2, uint32_t& r3,
                                      uint32_t addr) {
    asm volatile("ldmatrix.sync.aligned.m8n8.x4.shared.b16 {%0,%1,%2,%3}, [%4];"
                 : "=r"(r0), "=r"(r1), "=r"(r2), "=r"(r3) : "r"(addr));
}

// bf16 tensor-core MMA: D(16x8,f32) += A(16x16) * B(16x8)
__device__ __forceinline__ void mma_bf16(float* c, const uint32_t* a, const uint32_t* b) {
    asm volatile(
        "mma.sync.aligned.m16n8k16.row.col.f32.bf16.bf16.f32 "
        "{%0,%1,%2,%3}, {%4,%5,%6,%7}, {%8,%9}, {%0,%1,%2,%3};"
        : "+f"(c[0]), "+f"(c[1]), "+f"(c[2]), "+f"(c[3])
        : "r"(a[0]), "r"(a[1]), "r"(a[2]), "r"(a[3]), "r"(b[0]), "r"(b[1]));
}

// quantize helper: q = clip(rint(v * f), -128, 127), packed as bf16 pair
__device__ __forceinline__ uint32_t quant2(float vx, float vy, float f) {
    float q0 = fminf(fmaxf(rintf(vx * f), -128.f), 127.f);
    float q1 = fminf(fmaxf(rintf(vy * f), -128.f), 127.f);
    unsigned short h0 = __bfloat16_as_ushort(__float2bfloat16_rn(q0));
    unsigned short h1 = __bfloat16_as_ushort(__float2bfloat16_rn(q1));
    return (uint32_t)h0 | ((uint32_t)h1 << 16);
}

// ------------------- fused: weight sign-pack (both) + actq(x) in one launch -------------------
__global__ void pack_actq_kernel(const float* __restrict__ w1, const float* __restrict__ w2,
                                 const float* __restrict__ x) {
    int tid = threadIdx.x;

    if (blockIdx.x < 2048) {
        // ---- pack half ----
        int half = blockIdx.x >> 10;               // 0: w1, 1: w2
        int blk = blockIdx.x & 1023;
        const float* w = half ? w2 : w1;
        __nv_bfloat16* ws = half ? g_w2s : g_w1s;
        float* partial = half ? g_part2 : g_part1;
        const int n4 = (INNERX * DIMX) >> 2;
        int gid = blk * 256 + tid;
        const float4* w4 = (const float4*)w;
        float s = 0.f;
        for (int i = gid; i < n4; i += 1024 * 256) {
            float4 v = w4[i];
            s += fabsf(v.x) + fabsf(v.y) + fabsf(v.z) + fabsf(v.w);
            unsigned short h0 = __bfloat16_as_ushort(__float2bfloat16_rn((v.x > 0.f) ? 1.f : ((v.x < 0.f) ? -1.f : 0.f)));
            unsigned short h1 = __bfloat16_as_ushort(__float2bfloat16_rn((v.y > 0.f) ? 1.f : ((v.y < 0.f) ? -1.f : 0.f)));
            unsigned short h2 = __bfloat16_as_ushort(__float2bfloat16_rn((v.z > 0.f) ? 1.f : ((v.z < 0.f) ? -1.f : 0.f)));
            unsigned short h3 = __bfloat16_as_ushort(__float2bfloat16_rn((v.w > 0.f) ? 1.f : ((v.w < 0.f) ? -1.f : 0.f)));
            uint2 u = make_uint2((uint32_t)h0 | ((uint32_t)h1 << 16),
                                 (uint32_t)h2 | ((uint32_t)h3 << 16));
            *(uint2*)(ws + (size_t)i * 4) = u;
        }
        for (int o = 16; o; o >>= 1) s += __shfl_xor_sync(0xffffffffu, s, o);
        __shared__ float r[8];
        if ((tid & 31) == 0) r[tid >> 5] = s;
        __syncthreads();
        if (tid == 0) {
            float S = 0.f;
            for (int i = 0; i < 8; i++) S += r[i];
            partial[blk] = S;
        }
        return;
    }

    // ---- actq(x) half (row length DIMX) ----
    extern __shared__ float srow[];    // DIMX floats
    __shared__ float red_s[8], red_m[8];
    __shared__ float bc_f;

    const float dscale = 0.022097086912079608f;   // 2048^-0.5
    int row = blockIdx.x - 2048;
    const float4* src = (const float4*)(x + (size_t)row * DIMX);
    const int n4 = DIMX >> 2;

    float ss = 0.f, mx = 0.f;
    for (int i = tid; i < n4; i += 256) {
        float4 v = src[i];
        ((float4*)srow)[i] = v;
        ss += v.x * v.x + v.y * v.y + v.z * v.z + v.w * v.w;
        mx = fmaxf(mx, fmaxf(fmaxf(fabsf(v.x), fabsf(v.y)), fmaxf(fabsf(v.z), fabsf(v.w))));
    }
    for (int o = 16; o; o >>= 1) {
        ss += __shfl_xor_sync(0xffffffffu, ss, o);
        mx = fmaxf(mx, __shfl_xor_sync(0xffffffffu, mx, o));
    }
    if ((tid & 31) == 0) { red_s[tid >> 5] = ss; red_m[tid >> 5] = mx; }
    __syncthreads();
    if (tid == 0) {
        float S = 0.f, M = 0.f;
        for (int i = 0; i < 8; i++) { S += red_s[i]; M = fmaxf(M, red_m[i]); }
        float rms = sqrtf(S / (float)DIMX + 1e-6f);
        float mxn = (M / rms) * dscale;            // == max over normalized |x| (monotone)
        float s_eff = fmaxf(mxn, 1e-5f);
        bc_f = (dscale / rms) * (127.0f / s_eff);  // single fused x -> quant-grid factor
        g_xsr[row] = s_eff / 127.0f;
    }
    __syncthreads();

    float f = bc_f;
    uint2* qout = (uint2*)(g_xq + (size_t)row * DIMX);
    for (int i = tid; i < n4; i += 256) {
        float4 v = ((float4*)srow)[i];
        qout[i] = make_uint2(quant2(v.x, v.y, f), quant2(v.z, v.w, f));
    }
}

__global__ void finalize_kernel() {
    __shared__ float sh[1024];
    int t = threadIdx.x;
    const float invn = 1.0f / (float)((size_t)INNERX * DIMX);
    sh[t] = g_part1[t];
    __syncthreads();
    for (int o = 512; o; o >>= 1) { if (t < o) sh[t] += sh[t + o]; __syncthreads(); }
    if (t == 0) g_wscale[0] = sh[0] * invn;
    __syncthreads();
    sh[t] = g_part2[t];
    __syncthreads();
    for (int o = 512; o; o >>= 1) { if (t < o) sh[t] += sh[t + o]; __syncthreads(); }
    if (t == 0) g_wscale[1] = sh[0] * invn;
}

// ---------- single-pass quant of h (stats precomputed in GEMM1 epilogue) ----------
__global__ void act_quant_h_kernel(float dscale) {
    __shared__ float sred[64], mred[64];
    __shared__ float bc_f;

    int row = blockIdx.x;
    int tid = threadIdx.x;

    if (tid < 64) {
        sred[tid] = g_hss[(size_t)row * 64 + tid];
        mred[tid] = g_hmx[(size_t)row * 64 + tid];
    }
    __syncthreads();
    if (tid == 0) {
        float S = 0.f, M = 0.f;
        for (int i = 0; i < 64; i++) { S += sred[i]; M = fmaxf(M, mred[i]); }   // fixed order
        float rms = sqrtf(S / (float)INNERX + 1e-6f);
        float mxn = (M / rms) * dscale;
        float s_eff = fmaxf(mxn, 1e-5f);
        bc_f = (dscale / rms) * (127.0f / s_eff);
        g_hsr[row] = s_eff / 127.0f;
    }
    __syncthreads();

    float f = bc_f;
    const float4* src = (const float4*)(g_h + (size_t)row * INNERX);
    uint2* qout = (uint2*)(g_hq + (size_t)row * INNERX);
    const int n4 = INNERX >> 2;
#pragma unroll
    for (int i = tid; i < n4; i += 256) {
        float4 v = src[i];
        qout[i] = make_uint2(quant2(v.x, v.y, f), quant2(v.z, v.w, f));
    }
}

// ---------- bf16 GEMM (R8 frozen mainloop): BM=128 BN=128 BK=64, 256 thr, 2 CTAs/SM, 3-stage ----------
static constexpr int ABYTES = 128 * 128;   // 16 KB / stage
static constexpr int BBYTES = 128 * 128;   // 16 KB / stage
static constexpr int STG = 3;
static constexpr int SMEM_DYN = STG * (ABYTES + BBYTES);   // 96 KB -> 2 CTAs/SM

__device__ __forceinline__ void load_tile(uint32_t sAbuf, uint32_t sBbuf,
                                          const char* Ag, const char* Bg,
                                          int rowBase, int colBase,
                                          size_t ldBytes, int ktile, int tid) {
    size_t kofs = (size_t)ktile * 128;   // 64 bf16 = 128 bytes per K tile
#pragma unroll
    for (int i = 0; i < 8; i++) {
        int c = tid + i * 256;
        if (i < 4) {                      // A: 1024 chunks (128 rows x 8 x 16B)
            int row = c >> 3, seg = c & 7;
            const char* src = Ag + (size_t)(rowBase + row) * ldBytes + kofs + seg * 16;
            cp16(sAbuf + SWZ128(row * 128 + seg * 16), src);
        } else {                          // B: 1024 chunks (128 rows x 8 x 16B)
            int cb = c - 1024;
            int row = cb >> 3, seg = cb & 7;
            const char* src = Bg + (size_t)(colBase + row) * ldBytes + kofs + seg * 16;
            cp16(sBbuf + SWZ128(row * 128 + seg * 16), src);
        }
    }
}

template <bool GELU>
__global__ __launch_bounds__(256, 2)
void gemm_kernel(const float* __restrict__ bias, float* __restrict__ out_param, int sel) {
    extern __shared__ char dyn[];
    uint32_t base = smem_u32(dyn);
    int tid = threadIdx.x;
    int wid = tid >> 5;
    int lane = tid & 31;

    const __nv_bfloat16* Ag = sel ? g_hq : g_xq;
    const __nv_bfloat16* Bg = sel ? g_w2s : g_w1s;
    float* out = sel ? out_param : g_h;
    const float* srv = sel ? g_hsr : g_xsr;
    const int K = sel ? INNERX : DIMX;
    const int NK = K >> 6;                       // K / 64
    const int ldOut = sel ? DIMX : INNERX;
    const size_t ldBytes = (size_t)K * 2;

    int rowBase = blockIdx.y * 128;
    int colBase = blockIdx.x * 128;

    uint32_t sA = base;
    uint32_t sB = base + STG * ABYTES;

    // warp tiling: 2(M) x 4(N) warps, 64x32 per warp
    int wm = wid & 1, wn = wid >> 1;
    int R = wm * 64, C = wn * 32;
    int g = lane >> 2;                 // accumulator row group

    // A ldsm x4: matrices {m0-7,k0-7},{m8-15,k0-7},{m0-7,k8-15},{m8-15,k8-15}
    int aRow = R + (lane & 7) + ((lane >> 3) & 1) * 8;       // + mi*16
    uint32_t aRowOff = (uint32_t)aRow * 128;
    uint32_t aSwz = (uint32_t)((lane & 7) << 4);
    uint32_t aKseg = (uint32_t)((lane >> 4) * 16);
    // B ldsm x4: matrices {n0-7,k0-7},{n0-7,k8-15},{n8-15,k0-7},{n8-15,k8-15}
    int bg = lane >> 3;
    int bRow = C + (lane & 7) + ((bg >> 1) * 8);             // + nj2*16
    uint32_t bRowOff = (uint32_t)bRow * 128;
    uint32_t bSwz = (uint32_t)((lane & 7) << 4);
    uint32_t bKseg = (uint32_t)((bg & 1) * 16);

    float acc[4][4][4];
#pragma unroll
    for (int mi = 0; mi < 4; mi++)
#pragma unroll
        for (int ni = 0; ni < 4; ni++)
#pragma unroll
            for (int r = 0; r < 4; r++) acc[mi][ni][r] = 0.f;

    // prologue: 2 tiles in flight
    load_tile(sA, sB, (const char*)Ag, (const char*)Bg, rowBase, colBase, ldBytes, 0, tid);
    CP_COMMIT();
    load_tile(sA + ABYTES, sB + BBYTES, (const char*)Ag, (const char*)Bg, rowBase, colBase, ldBytes, 1, tid);
    CP_COMMIT();

    int buf = 0;
    for (int kb = 0; kb < NK; kb++) {
        CP_WAIT(1);          // tile kb landed
        __syncthreads();     // all warps finished compute of kb-1 (frees staging buffer)

        int kp = kb + 2;
        int nbuf = buf + 1; if (nbuf == STG) nbuf = 0;
        int pbuf = nbuf + 1; if (pbuf == STG) pbuf = 0;
        if (kp < NK) {
            load_tile(sA + pbuf * ABYTES, sB + pbuf * BBYTES,
                      (const char*)Ag, (const char*)Bg, rowBase, colBase, ldBytes, kp, tid);
        }
        CP_COMMIT();

        uint32_t aB = sA + buf * ABYTES;
        uint32_t bB = sB + buf * BBYTES;
#pragma unroll
        for (int ks = 0; ks < 4; ks++) {    // 4 x k16 within BK=64
            uint32_t a[4][4];
#pragma unroll
            for (int mi = 0; mi < 4; mi++) {
                uint32_t addr = aB + aRowOff + (uint32_t)mi * 2048 +
                                (((uint32_t)ks * 32 + aKseg) ^ aSwz);
                ldsm4(a[mi][0], a[mi][1], a[mi][2], a[mi][3], addr);
            }
            uint32_t b[4][2];
#pragma unroll
            for (int nj = 0; nj < 2; nj++) {
                uint32_t addr = bB + bRowOff + (uint32_t)nj * 2048 +
                                (((uint32_t)ks * 32 + bKseg) ^ bSwz);
                ldsm4(b[2 * nj][0], b[2 * nj][1], b[2 * nj + 1][0], b[2 * nj + 1][1], addr);
            }
#pragma unroll
            for (int mi = 0; mi < 4; mi++)
#pragma unroll
                for (int ni = 0; ni < 4; ni++)
                    mma_bf16(acc[mi][ni], a[mi], b[ni]);
        }
        buf = nbuf;
    }

    // stats scratch reuses pipeline smem — must be past all warps' last ldsm
    float* sstats = (float*)dyn;            // [128][4]
    float* mstats = (float*)(dyn + 2048);   // [128][4]
    if (GELU) __syncthreads();

    // epilogue: accumulators are exact integer counts in fp32
    float wsc = g_wscale[sel];
    int t2 = (lane & 3) * 2;
#pragma unroll
    for (int mi = 0; mi < 4; mi++) {
        int r0 = rowBase + R + mi * 16 + g;
        int r1 = r0 + 8;
        float f0 = wsc * __ldg(&srv[r0]);
        float f1 = wsc * __ldg(&srv[r1]);
        float* o0 = out + (size_t)r0 * ldOut + colBase + C + t2;
        float* o1 = out + (size_t)r1 * ldOut + colBase + C + t2;
        const float* bp = bias + colBase + C + t2;
        float ss0 = 0.f, mx0 = 0.f, ss1 = 0.f, mx1 = 0.f;
#pragma unroll
        for (int ni = 0; ni < 4; ni++) {
            float2 v0, v1;
            v0.x = acc[mi][ni][0] * f0 + __ldg(bp + ni * 8 + 0);
            v0.y = acc[mi][ni][1] * f0 + __ldg(bp + ni * 8 + 1);
            v1.x = acc[mi][ni][2] * f1 + __ldg(bp + ni * 8 + 0);
            v1.y = acc[mi][ni][3] * f1 + __ldg(bp + ni * 8 + 1);
            if (GELU) {
                v0.x = 0.5f * v0.x * (1.0f + erff(v0.x * 0.70710678118654752f));
                v0.y = 0.5f * v0.y * (1.0f + erff(v0.y * 0.70710678118654752f));
                v1.x = 0.5f * v1.x * (1.0f + erff(v1.x * 0.70710678118654752f));
                v1.y = 0.5f * v1.y * (1.0f + erff(v1.y * 0.70710678118654752f));
                ss0 += v0.x * v0.x + v0.y * v0.y;
                ss1 += v1.x * v1.x + v1.y * v1.y;
                mx0 = fmaxf(mx0, fmaxf(fabsf(v0.x), fabsf(v0.y)));
                mx1 = fmaxf(mx1, fmaxf(fabsf(v1.x), fabsf(v1.y)));
            }
            *(float2*)(o0 + ni * 8) = v0;
            *(float2*)(o1 + ni * 8) = v1;
        }
        if (GELU) {
            // quad reduce: lanes of one quad (same g) hold the same rows
#pragma unroll
            for (int o = 1; o <= 2; o <<= 1) {
                ss0 += __shfl_xor_sync(0xffffffffu, ss0, o);
                ss1 += __shfl_xor_sync(0xffffffffu, ss1, o);
                mx0 = fmaxf(mx0, __shfl_xor_sync(0xffffffffu, mx0, o));
                mx1 = fmaxf(mx1, __shfl_xor_sync(0xffffffffu, mx1, o));
            }
            if ((lane & 3) == 0) {
                int rl0 = R + mi * 16 + g;
                int rl1 = rl0 + 8;
                sstats[rl0 * 4 + wn] = ss0;
                mstats[rl0 * 4 + wn] = mx0;
                sstats[rl1 * 4 + wn] = ss1;
                mstats[rl1 * 4 + wn] = mx1;
            }
        }
    }

    if (GELU) {
        __syncthreads();
        if (tid < 128) {
            float S = sstats[tid * 4] + sstats[tid * 4 + 1] + sstats[tid * 4 + 2] + sstats[tid * 4 + 3];
            float M = fmaxf(fmaxf(mstats[tid * 4], mstats[tid * 4 + 1]),
                            fmaxf(mstats[tid * 4 + 2], mstats[tid * 4 + 3]));
            size_t idx = (size_t)(rowBase + tid) * 64 + blockIdx.x;
            g_hss[idx] = S;
            g_hmx[idx] = M;
        }
    }
}

// ------------------------- launch -------------------------
extern "C" void kernel_launch(void* const* d_in, const int* in_sizes, int n_in,
                              void* d_out, int out_size) {
    const float* x  = (const float*)d_in[0];
    const float* w1 = (const float*)d_in[1];
    const float* b1 = (const float*)d_in[2];
    const float* w2 = (const float*)d_in[3];
    const float* b2 = (const float*)d_in[4];
    float* out = (float*)d_out;

    cudaFuncSetAttribute(gemm_kernel<true>,   cudaFuncAttributeMaxDynamicSharedMemorySize, SMEM_DYN);
    cudaFuncSetAttribute(gemm_kernel<false>,  cudaFuncAttributeMaxDynamicSharedMemorySize, SMEM_DYN);
    cudaFuncSetAttribute(pack_actq_kernel,    cudaFuncAttributeMaxDynamicSharedMemorySize, DIMX * 4);

    // 1. fused: weight pack (both) + actq(x)
    pack_actq_kernel<<<2048 + TOKX, 256, DIMX * 4>>>(w1, w2, x);
    // 2. weight scales
    finalize_kernel<<<1, 1024>>>();
    // 3. GEMM1 + bias + exact GELU -> g_h, + per-(row,tile) quant stats
    gemm_kernel<true><<<dim3(INNERX / 128, TOKX / 128), 256, SMEM_DYN>>>(b1, nullptr, 0);
    // 4. single-pass quant of h (stats from epilogue)
    act_quant_h_kernel<<<TOKX, 256>>>(0.011048543456039804f /* 8192^-0.5 */);
    // 5. GEMM2 + bias -> out
    gemm_kernel<false><<<dim3(DIMX / 128, TOKX / 128), 256, SMEM_DYN>>>(b2, out, 1);
}

// round 17
// speedup vs baseline: 1.0326x; 1.0326x over previous
#include <cuda_runtime.h>
#include <cuda_bf16.h>
#include <cstdint>
#include <math.h>

#define DIMX   2048
#define INNERX 8192
#define TOKX   8192

// ------------------------- device-global scratch -------------------------
__device__ __nv_bfloat16 g_w1s[(size_t)INNERX * DIMX];   // sign(w1) in {-1,0,1} (bf16)
__device__ __nv_bfloat16 g_w2s[(size_t)DIMX * INNERX];   // sign(w2)
__device__ __nv_bfloat16 g_xq[(size_t)TOKX * DIMX];      // quantized activations (integer-valued bf16)
__device__ __nv_bfloat16 g_hq[(size_t)TOKX * INNERX];
__device__ float  g_h[(size_t)TOKX * INNERX];            // fp32 hidden after GELU
__device__ float  g_xsr[TOKX];                           // per-token 1/scale (layer 1)
__device__ float  g_hsr[TOKX];                           // per-token 1/scale (layer 2)
__device__ float  g_part1[1024];
__device__ float  g_part2[1024];
__device__ float  g_wscale[2];                           // mean|w1|, mean|w2|

// ------------------------- helpers -------------------------
__device__ __forceinline__ uint32_t smem_u32(const void* p) {
    uint32_t a;
    asm("{ .reg .u64 t; cvta.to.shared.u64 t, %1; cvt.u32.u64 %0, t; }" : "=r"(a) : "l"(p));
    return a;
}
#define SWZ128(b) ((b) ^ (((b) >> 3) & 0x70))

__device__ __forceinline__ void cp16(uint32_t dst, const void* src) {
    asm volatile("cp.async.cg.shared.global [%0], [%1], 16;" :: "r"(dst), "l"(src) : "memory");
}
#define CP_COMMIT() asm volatile("cp.async.commit_group;" ::: "memory")
#define CP_WAIT(n)  asm volatile("cp.async.wait_group %0;" :: "n"(n) : "memory")

__device__ __forceinline__ void ldsm4(uint32_t& r0, uint32_t& r1, uint32_t& r2, uint32_t& r3,
                                      uint32_t addr) {
    asm volatile("ldmatrix.sync.aligned.m8n8.x4.shared.b16 {%0,%1,%2,%3}, [%4];"
                 : "=r"(r0), "=r"(r1), "=r"(r2), "=r"(r3) : "r"(addr));
}

// bf16 tensor-core MMA: D(16x8,f32) += A(16x16) * B(16x8)
__device__ __forceinline__ void mma_bf16(float* c, const uint32_t* a, const uint32_t* b) {
    asm volatile(
        "mma.sync.aligned.m16n8k16.row.col.f32.bf16.bf16.f32 "
        "{%0,%1,%2,%3}, {%4,%5,%6,%7}, {%8,%9}, {%0,%1,%2,%3};"
        : "+f"(c[0]), "+f"(c[1]), "+f"(c[2]), "+f"(c[3])
        : "r"(a[0]), "r"(a[1]), "r"(a[2]), "r"(a[3]), "r"(b[0]), "r"(b[1]));
}

// quantize helper: q = clip(rint(v * f), -128, 127), packed as bf16 pair
__device__ __forceinline__ uint32_t quant2(float vx, float vy, float f) {
    float q0 = fminf(fmaxf(rintf(vx * f), -128.f), 127.f);
    float q1 = fminf(fmaxf(rintf(vy * f), -128.f), 127.f);
    unsigned short h0 = __bfloat16_as_ushort(__float2bfloat16_rn(q0));
    unsigned short h1 = __bfloat16_as_ushort(__float2bfloat16_rn(q1));
    return (uint32_t)h0 | ((uint32_t)h1 << 16);
}

// ------------------- fused: weight sign-pack (both) + actq(x) in one launch -------------------
__global__ void pack_actq_kernel(const float* __restrict__ w1, const float* __restrict__ w2,
                                 const float* __restrict__ x) {
    int tid = threadIdx.x;

    if (blockIdx.x < 2048) {
        // ---- pack half ----
        int half = blockIdx.x >> 10;               // 0: w1, 1: w2
        int blk = blockIdx.x & 1023;
        const float* w = half ? w2 : w1;
        __nv_bfloat16* ws = half ? g_w2s : g_w1s;
        float* partial = half ? g_part2 : g_part1;
        const int n4 = (INNERX * DIMX) >> 2;
        int gid = blk * 256 + tid;
        const float4* w4 = (const float4*)w;
        float s = 0.f;
        for (int i = gid; i < n4; i += 1024 * 256) {
            float4 v = w4[i];
            s += fabsf(v.x) + fabsf(v.y) + fabsf(v.z) + fabsf(v.w);
            unsigned short h0 = __bfloat16_as_ushort(__float2bfloat16_rn((v.x > 0.f) ? 1.f : ((v.x < 0.f) ? -1.f : 0.f)));
            unsigned short h1 = __bfloat16_as_ushort(__float2bfloat16_rn((v.y > 0.f) ? 1.f : ((v.y < 0.f) ? -1.f : 0.f)));
            unsigned short h2 = __bfloat16_as_ushort(__float2bfloat16_rn((v.z > 0.f) ? 1.f : ((v.z < 0.f) ? -1.f : 0.f)));
            unsigned short h3 = __bfloat16_as_ushort(__float2bfloat16_rn((v.w > 0.f) ? 1.f : ((v.w < 0.f) ? -1.f : 0.f)));
            uint2 u = make_uint2((uint32_t)h0 | ((uint32_t)h1 << 16),
                                 (uint32_t)h2 | ((uint32_t)h3 << 16));
            *(uint2*)(ws + (size_t)i * 4) = u;
        }
        for (int o = 16; o; o >>= 1) s += __shfl_xor_sync(0xffffffffu, s, o);
        __shared__ float r[8];
        if ((tid & 31) == 0) r[tid >> 5] = s;
        __syncthreads();
        if (tid == 0) {
            float S = 0.f;
            for (int i = 0; i < 8; i++) S += r[i];
            partial[blk] = S;
        }
        return;
    }

    // ---- actq(x) half (row length DIMX) ----
    extern __shared__ float srow[];    // DIMX floats
    __shared__ float red_s[8], red_m[8];
    __shared__ float bc_f;

    const float dscale = 0.022097086912079608f;   // 2048^-0.5
    int row = blockIdx.x - 2048;
    const float4* src = (const float4*)(x + (size_t)row * DIMX);
    const int n4 = DIMX >> 2;

    float ss = 0.f, mx = 0.f;
    for (int i = tid; i < n4; i += 256) {
        float4 v = src[i];
        ((float4*)srow)[i] = v;
        ss += v.x * v.x + v.y * v.y + v.z * v.z + v.w * v.w;
        mx = fmaxf(mx, fmaxf(fmaxf(fabsf(v.x), fabsf(v.y)), fmaxf(fabsf(v.z), fabsf(v.w))));
    }
    for (int o = 16; o; o >>= 1) {
        ss += __shfl_xor_sync(0xffffffffu, ss, o);
        mx = fmaxf(mx, __shfl_xor_sync(0xffffffffu, mx, o));
    }
    if ((tid & 31) == 0) { red_s[tid >> 5] = ss; red_m[tid >> 5] = mx; }
    __syncthreads();
    if (tid == 0) {
        float S = 0.f, M = 0.f;
        for (int i = 0; i < 8; i++) { S += red_s[i]; M = fmaxf(M, red_m[i]); }
        float rms = sqrtf(S / (float)DIMX + 1e-6f);
        float mxn = (M / rms) * dscale;            // == max over normalized |x| (monotone)
        float s_eff = fmaxf(mxn, 1e-5f);
        bc_f = (dscale / rms) * (127.0f / s_eff);  // single fused x -> quant-grid factor
        g_xsr[row] = s_eff / 127.0f;
    }
    __syncthreads();

    float f = bc_f;
    uint2* qout = (uint2*)(g_xq + (size_t)row * DIMX);
    for (int i = tid; i < n4; i += 256) {
        float4 v = ((float4*)srow)[i];
        qout[i] = make_uint2(quant2(v.x, v.y, f), quant2(v.z, v.w, f));
    }
}

__global__ void finalize_kernel() {
    __shared__ float sh[1024];
    int t = threadIdx.x;
    const float invn = 1.0f / (float)((size_t)INNERX * DIMX);
    sh[t] = g_part1[t];
    __syncthreads();
    for (int o = 512; o; o >>= 1) { if (t < o) sh[t] += sh[t + o]; __syncthreads(); }
    if (t == 0) g_wscale[0] = sh[0] * invn;
    __syncthreads();
    sh[t] = g_part2[t];
    __syncthreads();
    for (int o = 512; o; o >>= 1) { if (t < o) sh[t] += sh[t + o]; __syncthreads(); }
    if (t == 0) g_wscale[1] = sh[0] * invn;
}

// ---------- actq(h): stash-free two-pass (pass-2 re-read hits L2; zero smem -> high occupancy) ----------
__global__ void act_quant_h_kernel(float dscale) {
    __shared__ float red_s[8], red_m[8];
    __shared__ float bc_f;

    int row = blockIdx.x;
    int tid = threadIdx.x;
    const float4* src = (const float4*)(g_h + (size_t)row * INNERX);
    const int n4 = INNERX >> 2;

    float ss = 0.f, mx = 0.f;
#pragma unroll 4
    for (int i = tid; i < n4; i += 256) {
        float4 v = src[i];
        ss += v.x * v.x + v.y * v.y + v.z * v.z + v.w * v.w;
        mx = fmaxf(mx, fmaxf(fmaxf(fabsf(v.x), fabsf(v.y)), fmaxf(fabsf(v.z), fabsf(v.w))));
    }
    for (int o = 16; o; o >>= 1) {
        ss += __shfl_xor_sync(0xffffffffu, ss, o);
        mx = fmaxf(mx, __shfl_xor_sync(0xffffffffu, mx, o));
    }
    if ((tid & 31) == 0) { red_s[tid >> 5] = ss; red_m[tid >> 5] = mx; }
    __syncthreads();
    if (tid == 0) {
        float S = 0.f, M = 0.f;
        for (int i = 0; i < 8; i++) { S += red_s[i]; M = fmaxf(M, red_m[i]); }
        float rms = sqrtf(S / (float)INNERX + 1e-6f);
        float mxn = (M / rms) * dscale;
        float s_eff = fmaxf(mxn, 1e-5f);
        bc_f = (dscale / rms) * (127.0f / s_eff);  // single fused factor
        g_hsr[row] = s_eff / 127.0f;
    }
    __syncthreads();

    float f = bc_f;
    uint2* qout = (uint2*)(g_hq + (size_t)row * INNERX);
#pragma unroll 4
    for (int i = tid; i < n4; i += 256) {
        float4 v = src[i];                         // L2 hit (row cached by pass 1)
        qout[i] = make_uint2(quant2(v.x, v.y, f), quant2(v.z, v.w, f));
    }
}

// ---------- bf16 GEMM (R8 frozen config): BM=128 BN=128 BK=64, 256 thr, 2 CTAs/SM, 3-stage ----------
static constexpr int ABYTES = 128 * 128;   // 16 KB / stage
static constexpr int BBYTES = 128 * 128;   // 16 KB / stage
static constexpr int STG = 3;
static constexpr int SMEM_DYN = STG * (ABYTES + BBYTES);   // 96 KB -> 2 CTAs/SM

__device__ __forceinline__ void load_tile(uint32_t sAbuf, uint32_t sBbuf,
                                          const char* Ag, const char* Bg,
                                          int rowBase, int colBase,
                                          size_t ldBytes, int ktile, int tid) {
    size_t kofs = (size_t)ktile * 128;   // 64 bf16 = 128 bytes per K tile
#pragma unroll
    for (int i = 0; i < 8; i++) {
        int c = tid + i * 256;
        if (i < 4) {                      // A: 1024 chunks (128 rows x 8 x 16B)
            int row = c >> 3, seg = c & 7;
            const char* src = Ag + (size_t)(rowBase + row) * ldBytes + kofs + seg * 16;
            cp16(sAbuf + SWZ128(row * 128 + seg * 16), src);
        } else {                          // B: 1024 chunks (128 rows x 8 x 16B)
            int cb = c - 1024;
            int row = cb >> 3, seg = cb & 7;
            const char* src = Bg + (size_t)(colBase + row) * ldBytes + kofs + seg * 16;
            cp16(sBbuf + SWZ128(row * 128 + seg * 16), src);
        }
    }
}

template <bool GELU>
__global__ __launch_bounds__(256, 2)
void gemm_kernel(const float* __restrict__ bias, float* __restrict__ out_param, int sel) {
    extern __shared__ char dyn[];
    uint32_t base = smem_u32(dyn);
    int tid = threadIdx.x;
    int wid = tid >> 5;
    int lane = tid & 31;

    const __nv_bfloat16* Ag = sel ? g_hq : g_xq;
    const __nv_bfloat16* Bg = sel ? g_w2s : g_w1s;
    float* out = sel ? out_param : g_h;
    const float* srv = sel ? g_hsr : g_xsr;
    const int K = sel ? INNERX : DIMX;
    const int NK = K >> 6;                       // K / 64
    const int ldOut = sel ? DIMX : INNERX;
    const size_t ldBytes = (size_t)K * 2;

    int rowBase = blockIdx.y * 128;
    int colBase = blockIdx.x * 128;

    uint32_t sA = base;
    uint32_t sB = base + STG * ABYTES;

    // warp tiling: 2(M) x 4(N) warps, 64x32 per warp
    int wm = wid & 1, wn = wid >> 1;
    int R = wm * 64, C = wn * 32;
    int g = lane >> 2;                 // accumulator row group

    // A ldsm x4: matrices {m0-7,k0-7},{m8-15,k0-7},{m0-7,k8-15},{m8-15,k8-15}
    int aRow = R + (lane & 7) + ((lane >> 3) & 1) * 8;       // + mi*16
    uint32_t aRowOff = (uint32_t)aRow * 128;
    uint32_t aSwz = (uint32_t)((lane & 7) << 4);
    uint32_t aKseg = (uint32_t)((lane >> 4) * 16);
    // B ldsm x4: matrices {n0-7,k0-7},{n0-7,k8-15},{n8-15,k0-7},{n8-15,k8-15}
    int bg = lane >> 3;
    int bRow = C + (lane & 7) + ((bg >> 1) * 8);             // + nj2*16
    uint32_t bRowOff = (uint32_t)bRow * 128;
    uint32_t bSwz = (uint32_t)((lane & 7) << 4);
    uint32_t bKseg = (uint32_t)((bg & 1) * 16);

    float acc[4][4][4];
#pragma unroll
    for (int mi = 0; mi < 4; mi++)
#pragma unroll
        for (int ni = 0; ni < 4; ni++)
#pragma unroll
            for (int r = 0; r < 4; r++) acc[mi][ni][r] = 0.f;

    // prologue: 2 tiles in flight
    load_tile(sA, sB, (const char*)Ag, (const char*)Bg, rowBase, colBase, ldBytes, 0, tid);
    CP_COMMIT();
    load_tile(sA + ABYTES, sB + BBYTES, (const char*)Ag, (const char*)Bg, rowBase, colBase, ldBytes, 1, tid);
    CP_COMMIT();

    int buf = 0;
    for (int kb = 0; kb < NK; kb++) {
        CP_WAIT(1);          // tile kb landed
        __syncthreads();     // all warps finished compute of kb-1 (frees staging buffer)

        int kp = kb + 2;
        int nbuf = buf + 1; if (nbuf == STG) nbuf = 0;
        int pbuf = nbuf + 1; if (pbuf == STG) pbuf = 0;
        if (kp < NK) {
            load_tile(sA + pbuf * ABYTES, sB + pbuf * BBYTES,
                      (const char*)Ag, (const char*)Bg, rowBase, colBase, ldBytes, kp, tid);
        }
        CP_COMMIT();

        uint32_t aB = sA + buf * ABYTES;
        uint32_t bB = sB + buf * BBYTES;
#pragma unroll
        for (int ks = 0; ks < 4; ks++) {    // 4 x k16 within BK=64
            uint32_t a[4][4];
#pragma unroll
            for (int mi = 0; mi < 4; mi++) {
                uint32_t addr = aB + aRowOff + (uint32_t)mi * 2048 +
                                (((uint32_t)ks * 32 + aKseg) ^ aSwz);
                ldsm4(a[mi][0], a[mi][1], a[mi][2], a[mi][3], addr);
            }
            uint32_t b[4][2];
#pragma unroll
            for (int nj = 0; nj < 2; nj++) {
                uint32_t addr = bB + bRowOff + (uint32_t)nj * 2048 +
                                (((uint32_t)ks * 32 + bKseg) ^ bSwz);
                ldsm4(b[2 * nj][0], b[2 * nj][1], b[2 * nj + 1][0], b[2 * nj + 1][1], addr);
            }
#pragma unroll
            for (int mi = 0; mi < 4; mi++)
#pragma unroll
                for (int ni = 0; ni < 4; ni++)
                    mma_bf16(acc[mi][ni], a[mi], b[ni]);
        }
        buf = nbuf;
    }

    // epilogue: accumulators are exact integer counts in fp32
    float wsc = g_wscale[sel];
    int t2 = (lane & 3) * 2;
#pragma unroll
    for (int mi = 0; mi < 4; mi++) {
        int r0 = rowBase + R + mi * 16 + g;
        int r1 = r0 + 8;
        float f0 = wsc * __ldg(&srv[r0]);
        float f1 = wsc * __ldg(&srv[r1]);
        float* o0 = out + (size_t)r0 * ldOut + colBase + C + t2;
        float* o1 = out + (size_t)r1 * ldOut + colBase + C + t2;
        const float* bp = bias + colBase + C + t2;
#pragma unroll
        for (int ni = 0; ni < 4; ni++) {
            float2 v0, v1;
            v0.x = acc[mi][ni][0] * f0 + __ldg(bp + ni * 8 + 0);
            v0.y = acc[mi][ni][1] * f0 + __ldg(bp + ni * 8 + 1);
            v1.x = acc[mi][ni][2] * f1 + __ldg(bp + ni * 8 + 0);
            v1.y = acc[mi][ni][3] * f1 + __ldg(bp + ni * 8 + 1);
            if (GELU) {
                v0.x = 0.5f * v0.x * (1.0f + erff(v0.x * 0.70710678118654752f));
                v0.y = 0.5f * v0.y * (1.0f + erff(v0.y * 0.70710678118654752f));
                v1.x = 0.5f * v1.x * (1.0f + erff(v1.x * 0.70710678118654752f));
                v1.y = 0.5f * v1.y * (1.0f + erff(v1.y * 0.70710678118654752f));
            }
            *(float2*)(o0 + ni * 8) = v0;
            *(float2*)(o1 + ni * 8) = v1;
        }
    }
}

// ------------------------- launch -------------------------
extern "C" void kernel_launch(void* const* d_in, const int* in_sizes, int n_in,
                              void* d_out, int out_size) {
    const float* x  = (const float*)d_in[0];
    const float* w1 = (const float*)d_in[1];
    const float* b1 = (const float*)d_in[2];
    const float* w2 = (const float*)d_in[3];
    const float* b2 = (const float*)d_in[4];
    float* out = (float*)d_out;

    cudaFuncSetAttribute(gemm_kernel<true>,   cudaFuncAttributeMaxDynamicSharedMemorySize, SMEM_DYN);
    cudaFuncSetAttribute(gemm_kernel<false>,  cudaFuncAttributeMaxDynamicSharedMemorySize, SMEM_DYN);
    cudaFuncSetAttribute(pack_actq_kernel,    cudaFuncAttributeMaxDynamicSharedMemorySize, DIMX * 4);

    // 1. fused: weight pack (both) + actq(x)
    pack_actq_kernel<<<2048 + TOKX, 256, DIMX * 4>>>(w1, w2, x);
    // 2. weight scales
    finalize_kernel<<<1, 1024>>>();
    // 3. GEMM1 + bias + exact GELU -> g_h
    gemm_kernel<true><<<dim3(INNERX / 128, TOKX / 128), 256, SMEM_DYN>>>(b1, nullptr, 0);
    // 4. quant of h (stash-free)
    act_quant_h_kernel<<<TOKX, 256>>>(0.011048543456039804f /* 8192^-0.5 */);
    // 5. GEMM2 + bias -> out
    gemm_kernel<false><<<dim3(DIMX / 128, TOKX / 128), 256, SMEM_DYN>>>(b2, out, 1);
}